// round 7
// baseline (speedup 1.0000x reference)
#include <cuda_runtime.h>

#define IW 1920
#define IH 1080
#define IB 8
#define NPIX (IW * IH)
#define NTOT (IB * NPIX)
#define WPR  (IW / 32)            // 60 packed words per row
#define NWORDS (NTOT / 32)        // 518400
#define BORDER_WORDS_PER_IMG (60 + 60 + 1078 * 2)   // 2276

#define TH 24                     // output tile height (1080/24 = 45)

// Scratch (no cudaMalloc allowed)
__device__ unsigned char g_dir[NTOT];
__device__ unsigned int  g_pe0[NWORDS], g_pl0[NWORDS];   // after NMS/threshold
__device__ unsigned int  g_pe1[NWORDS], g_pl1[NWORDS];   // after hysteresis iter 1

// Sobel with immediate weights (zero-weight terms skipped; original fmaf order)
__device__ __forceinline__ void sobel_px(const float (*gsm)[37], int r, int c,
                                         float& gxv, float& gyv) {
    const float v00 = gsm[r+0][c+0], v01 = gsm[r+0][c+1], v02 = gsm[r+0][c+2];
    const float v10 = gsm[r+1][c+0],                      v12 = gsm[r+1][c+2];
    const float v20 = gsm[r+2][c+0], v21 = gsm[r+2][c+1], v22 = gsm[r+2][c+2];
    float gx = 0.f;
    gx = fmaf(-0.125f, v00, gx);
    gx = fmaf( 0.125f, v02, gx);
    gx = fmaf(-0.25f,  v10, gx);
    gx = fmaf( 0.25f,  v12, gx);
    gx = fmaf(-0.125f, v20, gx);
    gx = fmaf( 0.125f, v22, gx);
    float gy = 0.f;
    gy = fmaf(-0.125f, v00, gy);
    gy = fmaf(-0.25f,  v01, gy);
    gy = fmaf(-0.125f, v02, gy);
    gy = fmaf( 0.125f, v20, gy);
    gy = fmaf( 0.25f,  v21, gy);
    gy = fmaf( 0.125f, v22, gy);
    gxv = gx; gyv = gy;
}

// ---------------------------------------------------------------------------
// Kernel 1: fused gaussian(5x5) + sobel + mag*255 + ang + NMS + threshold.
// Round-4 structure (3 smem arrays, per-pixel sobel recompute in stage 3),
// with all convolution weights as immediates (FFMA-imm).
// Border words (jnp.roll wrap) recomputed by k_border afterwards.
// ---------------------------------------------------------------------------
__global__ void k_fused(const float* __restrict__ x,
                        float* __restrict__ magOut, float* __restrict__ angOut) {
    // gaussian = [[2,4,5,4,2],[4,9,12,9,4],[5,12,15,12,5],[4,9,12,9,4],[2,4,5,4,2]]/159
    constexpr float GW[25] = {
        2.0f/159.0f, 4.0f/159.0f,  5.0f/159.0f, 4.0f/159.0f, 2.0f/159.0f,
        4.0f/159.0f, 9.0f/159.0f, 12.0f/159.0f, 9.0f/159.0f, 4.0f/159.0f,
        5.0f/159.0f,12.0f/159.0f, 15.0f/159.0f,12.0f/159.0f, 5.0f/159.0f,
        4.0f/159.0f, 9.0f/159.0f, 12.0f/159.0f, 9.0f/159.0f, 4.0f/159.0f,
        2.0f/159.0f, 4.0f/159.0f,  5.0f/159.0f, 4.0f/159.0f, 2.0f/159.0f };
    __shared__ float sin_[32][41];   // raw input, rows by-4..by+27, cols bx-4..bx+35
    __shared__ float gsm[28][37];    // smoothed/255, rows by-2..by+25, cols bx-2..bx+33
    __shared__ float magS[26][35];   // mag*255, rows by-1..by+24, cols bx-1..bx+33
    const int b  = blockIdx.z;
    const int bx = blockIdx.x * 32, by = blockIdx.y * TH;
    const int tx = threadIdx.x, ty = threadIdx.y;
    const int tid = ty * 32 + tx;
    const float* img = x + b * NPIX;
    // ---- stage 0: raw input tile (zero padded) ----
    for (int i = tid; i < 32 * 40; i += 256) {
        int r = i / 40, c = i % 40;
        int yy = by + r - 4, xx = bx + c - 4;
        float v = 0.f;
        if (yy >= 0 && yy < IH && xx >= 0 && xx < IW) v = img[yy * IW + xx];
        sin_[r][c] = v;
    }
    __syncthreads();
    // ---- stage 1: gaussian -> gsm (immediate weights, original fmaf order) ----
    for (int i = tid; i < 28 * 36; i += 256) {
        int r = i / 36, c = i % 36;
        int yy = by + r - 2, xx = bx + c - 2;
        float s = 0.f;
#pragma unroll
        for (int di = 0; di < 5; di++)
#pragma unroll
            for (int dj = 0; dj < 5; dj++)
                s = fmaf(GW[di * 5 + dj], sin_[r + di][c + dj], s);
        gsm[r][c] = (yy >= 0 && yy < IH && xx >= 0 && xx < IW) ? s * (1.0f / 255.0f) : 0.f;
    }
    __syncthreads();
    // ---- stage 2: sobel magnitude -> magS ----
    for (int i = tid; i < 26 * 34; i += 256) {
        int r = i / 34, c = i % 34;
        float gxv, gyv;
        sobel_px(gsm, r, c, gxv, gyv);
        magS[r][c] = sqrtf(gxv * gxv + gyv * gyv + 1e-6f) * 255.0f;
    }
    __syncthreads();
    // ---- stage 3: per-pixel angle + outputs + NMS (3 rows per thread) ----
    const bool colBorder = (blockIdx.x == 0) | (blockIdx.x == WPR - 1);
#pragma unroll
    for (int s = 0; s < 3; s++) {
        const int o = ty + 8 * s;            // output row within tile (warp-uniform)
        const int Y = by + o;
        const int idx = b * NPIX + Y * IW + (bx + tx);
        float gx_, gy_;
        sobel_px(gsm, o + 1, tx + 1, gx_, gy_);
        const float m255 = magS[o + 1][tx + 1];
        magOut[idx] = m255;
        float ang = atan2f(gy_, gx_);
        float t = ang + 3.14159274101257324f;            // float32(pi)
        if (t >= 6.28318548202514648f) t -= 6.28318548202514648f;   // == fmodf(t, 2pi)
        float deg = t * 57.2957801818847656f;            // float32(180/pi)
        float am = deg;
        if (am >= 180.0f) am -= 180.0f;                  // == fmodf(deg, 180)
        if (am >= 180.0f) am -= 180.0f;
        angOut[idx] = am;
        int q = (int)rintf(deg / 45.0f);                 // round-half-even == jnp.round
        const int cls = q & 3;
        if (Y == 0 || Y == IH - 1 || colBorder)
            g_dir[idx] = (unsigned char)cls;
        // NMS from smem (interior-valid; border words overwritten by k_border)
        const int r0 = o + 1, c0 = tx + 1;
        // cls0: (y,xr)/(y,xl)  cls1: (yd,xr)/(yu,x) [ref bug kept]
        // cls2: (yd,x)/(yu,x)  cls3: (yd,xl)/(yu,xr)
        int ar = (cls == 0) ? r0 : r0 + 1;
        int ac = (cls == 2) ? c0 : ((cls == 3) ? c0 - 1 : c0 + 1);
        int cr = (cls == 0) ? r0 : r0 - 1;
        int cc = (cls == 0) ? c0 - 1 : ((cls == 3) ? c0 + 1 : c0);
        float a = magS[ar][ac];
        float c = magS[cr][cc];
        float sup = (m255 > a && m255 > c) ? m255 : 0.f;
        unsigned we = __ballot_sync(0xffffffffu, sup > 150.0f);
        unsigned wl = __ballot_sync(0xffffffffu, sup >= 50.0f && sup < 150.0f);
        if (tx == 0) {
            const int widx = (b * IH + Y) * WPR + blockIdx.x;
            g_pe0[widx] = we;
            g_pl0[widx] = wl;
        }
    }
}

// ---------------------------------------------------------------------------
// Kernel 2: recompute NMS/threshold for border words (rows 0 & 1079, word
// cols 0 & 59) with jnp.roll wrap-around. One warp per word.
// ---------------------------------------------------------------------------
__global__ void k_border(const float* __restrict__ mag) {
    const int W = blockIdx.x * 8 + threadIdx.y;          // warp id
    const int lane = threadIdx.x;
    const int b = W / BORDER_WORDS_PER_IMG;
    const int u = W % BORDER_WORDS_PER_IMG;
    int y, w;
    if (u < 60)       { y = 0;        w = u; }
    else if (u < 120) { y = IH - 1;   w = u - 60; }
    else { int v = u - 120; y = 1 + (v >> 1); w = (v & 1) ? (WPR - 1) : 0; }
    const int x = w * 32 + lane;
    const float* p = mag + b * NPIX;
    const int idx = b * NPIX + y * IW + x;
    const float m0 = p[y * IW + x];
    const int xl = (x == 0) ? (IW - 1) : (x - 1);
    const int xr = (x == IW - 1) ? 0 : (x + 1);
    const int yu = (y == 0) ? (IH - 1) : (y - 1);
    const int yd = (y == IH - 1) ? 0 : (y + 1);
    const int cls = g_dir[idx];
    int ay = (cls == 0) ? y : yd;
    int ax = (cls == 2) ? x : ((cls == 3) ? xl : xr);
    int cy = (cls == 0) ? y : yu;
    int cx = (cls == 0) ? xl : ((cls == 3) ? xr : x);
    float a = p[ay * IW + ax];
    float c = p[cy * IW + cx];
    float sup = (m0 > a && m0 > c) ? m0 : 0.f;
    unsigned we = __ballot_sync(0xffffffffu, sup > 150.0f);
    unsigned wl = __ballot_sync(0xffffffffu, sup >= 50.0f && sup < 150.0f);
    if (lane == 0) {
        const int widx = (b * IH + y) * WPR + w;
        g_pe0[widx] = we;
        g_pl0[widx] = wl;
    }
}

// ---------------------------------------------------------------------------
// Bit helper: OR of {left,center,right} horizontal neighbors of a word row.
// ---------------------------------------------------------------------------
__device__ __forceinline__ unsigned hor3(unsigned L, unsigned M, unsigned R) {
    return M | (M << 1) | (M >> 1) | (L >> 31) | (R << 31);
}

// ---------------------------------------------------------------------------
// Kernel 3: hysteresis iteration 1, fully bit-packed, word per thread.
// ---------------------------------------------------------------------------
__global__ void k_hyst1() {
    const int t = blockIdx.x * 256 + threadIdx.x;
    const int w = t % WPR;
    const int rem = t / WPR;
    const int y = rem % IH;
    const int base = t - w;
    unsigned nbr = 0, e = 0;
#pragma unroll
    for (int dy = -1; dy <= 1; dy++) {
        const int yy = y + dy;
        if (yy < 0 || yy >= IH) continue;
        const int rb = base + dy * WPR;
        unsigned L = (w > 0)       ? g_pe0[rb + w - 1] : 0u;
        unsigned M =                 g_pe0[rb + w];
        unsigned R = (w < WPR - 1) ? g_pe0[rb + w + 1] : 0u;
        nbr |= hor3(L, M, R);
        if (dy == 0) e = M;
    }
    const unsigned l = g_pl0[t];
    const unsigned conn = nbr & l;
    g_pe1[t] = e | conn;
    g_pl1[t] = l & ~conn;
}

// ---------------------------------------------------------------------------
// Kernel 4: hysteresis iteration 2 + final edges*255 float store.
// ---------------------------------------------------------------------------
__global__ void k_hyst2(float* __restrict__ outE) {
    __shared__ float buf[256 * 33];
    const int t0 = blockIdx.x * 256;
    const int t = t0 + threadIdx.x;
    const int w = t % WPR;
    const int rem = t / WPR;
    const int y = rem % IH;
    const int base = t - w;
    unsigned nbr = 0, e = 0;
#pragma unroll
    for (int dy = -1; dy <= 1; dy++) {
        const int yy = y + dy;
        if (yy < 0 || yy >= IH) continue;
        const int rb = base + dy * WPR;
        unsigned L = (w > 0)       ? g_pe1[rb + w - 1] : 0u;
        unsigned M =                 g_pe1[rb + w];
        unsigned R = (w < WPR - 1) ? g_pe1[rb + w + 1] : 0u;
        nbr |= hor3(L, M, R);
        if (dy == 0) e = M;
    }
    const unsigned l = g_pl1[t];
    const unsigned enew = e | (nbr & l);
#pragma unroll
    for (int j = 0; j < 32; j++)
        buf[threadIdx.x * 33 + j] = ((enew >> j) & 1u) ? 255.0f : 0.0f;
    __syncthreads();
    const int gbase = t0 * 32;
#pragma unroll
    for (int i = 0; i < 32; i++) {
        const int k = i * 256 + threadIdx.x;
        outE[gbase + k] = buf[(k >> 5) * 33 + (k & 31)];
    }
}

extern "C" void kernel_launch(void* const* d_in, const int* in_sizes, int n_in,
                              void* d_out, int out_size) {
    const float* x = (const float*)d_in[0];
    float* out       = (float*)d_out;
    float* out_edges = out;
    float* out_mag   = out + NTOT;
    float* out_ang   = out + 2 * NTOT;

    dim3 blk(32, 8, 1);
    dim3 grd(IW / 32, IH / TH, IB);

    k_fused<<<grd, blk>>>(x, out_mag, out_ang);
    k_border<<<(IB * BORDER_WORDS_PER_IMG) / 8, blk>>>(out_mag);
    k_hyst1<<<NWORDS / 256, 256>>>();
    k_hyst2<<<NWORDS / 256, 256>>>(out_edges);
}

// round 8
// speedup vs baseline: 1.9769x; 1.9769x over previous
#include <cuda_runtime.h>

#define IW 1920
#define IH 1080
#define IB 8
#define NPIX (IW * IH)
#define NTOT (IB * NPIX)
#define WPR  (IW / 32)            // 60 packed words per row
#define NWORDS (NTOT / 32)        // 518400
#define BORDER_WORDS_PER_IMG (60 + 60 + 1078 * 2)   // 2276

#define TH 24                     // output tile height (1080/24 = 45)

// Scratch (no cudaMalloc allowed)
__device__ unsigned char g_dir[NTOT];
__device__ unsigned int  g_pe0[NWORDS], g_pl0[NWORDS];   // after NMS/threshold
__device__ unsigned int  g_pe1[NWORDS], g_pl1[NWORDS];   // after hysteresis iter 1

// Sobel with immediate weights (zero-weight terms skipped; original fmaf order).
// Window top-left = (r, c): reads gsm[r..r+2][c..c+2].
__device__ __forceinline__ void sobel_px(const float (*gsm)[40], int r, int c,
                                         float& gxv, float& gyv) {
    const float v00 = gsm[r+0][c+0], v01 = gsm[r+0][c+1], v02 = gsm[r+0][c+2];
    const float v10 = gsm[r+1][c+0],                      v12 = gsm[r+1][c+2];
    const float v20 = gsm[r+2][c+0], v21 = gsm[r+2][c+1], v22 = gsm[r+2][c+2];
    float gx = 0.f;
    gx = fmaf(-0.125f, v00, gx);
    gx = fmaf( 0.125f, v02, gx);
    gx = fmaf(-0.25f,  v10, gx);
    gx = fmaf( 0.25f,  v12, gx);
    gx = fmaf(-0.125f, v20, gx);
    gx = fmaf( 0.125f, v22, gx);
    float gy = 0.f;
    gy = fmaf(-0.125f, v00, gy);
    gy = fmaf(-0.25f,  v01, gy);
    gy = fmaf(-0.125f, v02, gy);
    gy = fmaf( 0.125f, v20, gy);
    gy = fmaf( 0.25f,  v21, gy);
    gy = fmaf( 0.125f, v22, gy);
    gxv = gx; gyv = gy;
}

// ---------------------------------------------------------------------------
// Kernel 1: fused gaussian(5x5) + sobel + mag*255 + ang + NMS + threshold.
// 4-col register-blocked gaussian (LDS.128), sobel once per pixel with
// gx/gy/mag carried in registers to stage 3.
// Border words (jnp.roll wrap) recomputed by k_border afterwards.
// ---------------------------------------------------------------------------
__global__ void k_fused(const float* __restrict__ x,
                        float* __restrict__ magOut, float* __restrict__ angOut) {
    // gaussian = [[2,4,5,4,2],[4,9,12,9,4],[5,12,15,12,5],[4,9,12,9,4],[2,4,5,4,2]]/159
    constexpr float GW[25] = {
        2.0f/159.0f, 4.0f/159.0f,  5.0f/159.0f, 4.0f/159.0f, 2.0f/159.0f,
        4.0f/159.0f, 9.0f/159.0f, 12.0f/159.0f, 9.0f/159.0f, 4.0f/159.0f,
        5.0f/159.0f,12.0f/159.0f, 15.0f/159.0f,12.0f/159.0f, 5.0f/159.0f,
        4.0f/159.0f, 9.0f/159.0f, 12.0f/159.0f, 9.0f/159.0f, 4.0f/159.0f,
        2.0f/159.0f, 4.0f/159.0f,  5.0f/159.0f, 4.0f/159.0f, 2.0f/159.0f };
    __shared__ float sin_[32][40];   // raw input, rows by-4..by+27, cols bx-4..bx+35
    __shared__ float gsm[28][40];    // smoothed/255, rows by-2..by+25, cols bx-2..bx+33 (36 used)
    __shared__ float magS[26][35];   // mag*255, rows by-1..by+24, cols bx-1..bx+32 (34 used)
    const int b  = blockIdx.z;
    const int bx = blockIdx.x * 32, by = blockIdx.y * TH;
    const int tx = threadIdx.x, ty = threadIdx.y;
    const int tid = ty * 32 + tx;
    const float* img = x + b * NPIX;
    // ---- stage 0: raw input tile (zero padded), div/mod-free ----
#pragma unroll
    for (int k = 0; k < 4; k++) {
        const int r = ty + 8 * k;
        const int yy = by + r - 4;
        {
            const int xx = bx + tx - 4;
            float v = 0.f;
            if (yy >= 0 && yy < IH && xx >= 0 && xx < IW) v = img[yy * IW + xx];
            sin_[r][tx] = v;
        }
        if (tx < 8) {
            const int xx = bx + tx + 28;     // (tx+32) - 4
            float v = 0.f;
            if (yy >= 0 && yy < IH && xx >= 0 && xx < IW) v = img[yy * IW + xx];
            sin_[r][tx + 32] = v;
        }
    }
    __syncthreads();
    // ---- stage 1: gaussian, 4 outputs per thread (28 rows x 9 groups = 252) ----
    if (tid < 252) {
        const int r = tid / 9;
        const int c0 = (tid - r * 9) * 4;
        float W[5][8];
#pragma unroll
        for (int di = 0; di < 5; di++) {
            const float4 lo = *(const float4*)&sin_[r + di][c0];
            const float4 hi = *(const float4*)&sin_[r + di][c0 + 4];
            W[di][0] = lo.x; W[di][1] = lo.y; W[di][2] = lo.z; W[di][3] = lo.w;
            W[di][4] = hi.x; W[di][5] = hi.y; W[di][6] = hi.z; W[di][7] = hi.w;
        }
        float s0 = 0.f, s1 = 0.f, s2 = 0.f, s3 = 0.f;
#pragma unroll
        for (int di = 0; di < 5; di++)
#pragma unroll
            for (int dj = 0; dj < 5; dj++) {
                const float wgt = GW[di * 5 + dj];
                s0 = fmaf(wgt, W[di][dj + 0], s0);
                s1 = fmaf(wgt, W[di][dj + 1], s1);
                s2 = fmaf(wgt, W[di][dj + 2], s2);
                s3 = fmaf(wgt, W[di][dj + 3], s3);
            }
        const int yy = by + r - 2;
        const bool rowOk = (yy >= 0 && yy < IH);
        const int xx0 = bx + c0 - 2;
        float4 o;
        o.x = (rowOk && xx0 + 0 >= 0 && xx0 + 0 < IW) ? s0 * (1.0f / 255.0f) : 0.f;
        o.y = (rowOk && xx0 + 1 >= 0 && xx0 + 1 < IW) ? s1 * (1.0f / 255.0f) : 0.f;
        o.z = (rowOk && xx0 + 2 >= 0 && xx0 + 2 < IW) ? s2 * (1.0f / 255.0f) : 0.f;
        o.w = (rowOk && xx0 + 3 >= 0 && xx0 + 3 < IW) ? s3 * (1.0f / 255.0f) : 0.f;
        *(float4*)&gsm[r][c0] = o;
    }
    __syncthreads();
    // ---- stage 2: sobel once per pixel; interior keeps gx/gy/mag in regs ----
    float gxr[3], gyr[3], mr[3];
#pragma unroll
    for (int s = 0; s < 3; s++) {
        const int r0 = ty + 8 * s + 1, c0 = tx + 1;
        sobel_px(gsm, r0, c0, gxr[s], gyr[s]);
        mr[s] = sqrtf(gxr[s] * gxr[s] + gyr[s] * gyr[s] + 1e-6f) * 255.0f;
        magS[r0][c0] = mr[s];
    }
    if (tid < 116) {   // halo ring of magS (26x34): rows 0 & 25 full, cols 0 & 33
        int r, c;
        if (tid < 34)      { r = 0;         c = tid; }
        else if (tid < 68) { r = 25;        c = tid - 34; }
        else if (tid < 92) { r = tid - 67;  c = 0; }          // rows 1..24
        else               { r = tid - 91;  c = 33; }         // rows 1..24
        float gxv, gyv;
        sobel_px(gsm, r, c, gxv, gyv);
        magS[r][c] = sqrtf(gxv * gxv + gyv * gyv + 1e-6f) * 255.0f;
    }
    __syncthreads();
    // ---- stage 3: per-pixel angle + outputs + NMS (3 rows per thread) ----
    const bool colBorder = (blockIdx.x == 0) | (blockIdx.x == WPR - 1);
#pragma unroll
    for (int s = 0; s < 3; s++) {
        const int o = ty + 8 * s;            // output row within tile (warp-uniform)
        const int Y = by + o;
        const int idx = b * NPIX + Y * IW + (bx + tx);
        const float gx_ = gxr[s];
        const float gy_ = gyr[s];
        const float m255 = mr[s];
        magOut[idx] = m255;
        float ang = atan2f(gy_, gx_);
        float t = ang + 3.14159274101257324f;            // float32(pi)
        if (t >= 6.28318548202514648f) t -= 6.28318548202514648f;   // == fmodf(t, 2pi)
        float deg = t * 57.2957801818847656f;            // float32(180/pi)
        float am = deg;
        if (am >= 180.0f) am -= 180.0f;                  // == fmodf(deg, 180)
        if (am >= 180.0f) am -= 180.0f;
        angOut[idx] = am;
        int q = (int)rintf(deg / 45.0f);                 // round-half-even == jnp.round
        const int cls = q & 3;
        if (Y == 0 || Y == IH - 1 || colBorder)
            g_dir[idx] = (unsigned char)cls;
        // NMS from smem (interior-valid; border words overwritten by k_border)
        const int r0 = o + 1, c0 = tx + 1;
        // cls0: (y,xr)/(y,xl)  cls1: (yd,xr)/(yu,x) [ref bug kept]
        // cls2: (yd,x)/(yu,x)  cls3: (yd,xl)/(yu,xr)
        int ar = (cls == 0) ? r0 : r0 + 1;
        int ac = (cls == 2) ? c0 : ((cls == 3) ? c0 - 1 : c0 + 1);
        int cr = (cls == 0) ? r0 : r0 - 1;
        int cc = (cls == 0) ? c0 - 1 : ((cls == 3) ? c0 + 1 : c0);
        float a = magS[ar][ac];
        float c = magS[cr][cc];
        float sup = (m255 > a && m255 > c) ? m255 : 0.f;
        unsigned we = __ballot_sync(0xffffffffu, sup > 150.0f);
        unsigned wl = __ballot_sync(0xffffffffu, sup >= 50.0f && sup < 150.0f);
        if (tx == 0) {
            const int widx = (b * IH + Y) * WPR + blockIdx.x;
            g_pe0[widx] = we;
            g_pl0[widx] = wl;
        }
    }
}

// ---------------------------------------------------------------------------
// Kernel 2: recompute NMS/threshold for border words (rows 0 & 1079, word
// cols 0 & 59) with jnp.roll wrap-around. One warp per word.
// ---------------------------------------------------------------------------
__global__ void k_border(const float* __restrict__ mag) {
    const int W = blockIdx.x * 8 + threadIdx.y;          // warp id
    const int lane = threadIdx.x;
    const int b = W / BORDER_WORDS_PER_IMG;
    const int u = W % BORDER_WORDS_PER_IMG;
    int y, w;
    if (u < 60)       { y = 0;        w = u; }
    else if (u < 120) { y = IH - 1;   w = u - 60; }
    else { int v = u - 120; y = 1 + (v >> 1); w = (v & 1) ? (WPR - 1) : 0; }
    const int x = w * 32 + lane;
    const float* p = mag + b * NPIX;
    const int idx = b * NPIX + y * IW + x;
    const float m0 = p[y * IW + x];
    const int xl = (x == 0) ? (IW - 1) : (x - 1);
    const int xr = (x == IW - 1) ? 0 : (x + 1);
    const int yu = (y == 0) ? (IH - 1) : (y - 1);
    const int yd = (y == IH - 1) ? 0 : (y + 1);
    const int cls = g_dir[idx];
    int ay = (cls == 0) ? y : yd;
    int ax = (cls == 2) ? x : ((cls == 3) ? xl : xr);
    int cy = (cls == 0) ? y : yu;
    int cx = (cls == 0) ? xl : ((cls == 3) ? xr : x);
    float a = p[ay * IW + ax];
    float c = p[cy * IW + cx];
    float sup = (m0 > a && m0 > c) ? m0 : 0.f;
    unsigned we = __ballot_sync(0xffffffffu, sup > 150.0f);
    unsigned wl = __ballot_sync(0xffffffffu, sup >= 50.0f && sup < 150.0f);
    if (lane == 0) {
        const int widx = (b * IH + y) * WPR + w;
        g_pe0[widx] = we;
        g_pl0[widx] = wl;
    }
}

// ---------------------------------------------------------------------------
// Bit helper: OR of {left,center,right} horizontal neighbors of a word row.
// ---------------------------------------------------------------------------
__device__ __forceinline__ unsigned hor3(unsigned L, unsigned M, unsigned R) {
    return M | (M << 1) | (M >> 1) | (L >> 31) | (R << 31);
}

// ---------------------------------------------------------------------------
// Kernel 3: hysteresis iteration 1, fully bit-packed, word per thread.
// ---------------------------------------------------------------------------
__global__ void k_hyst1() {
    const int t = blockIdx.x * 256 + threadIdx.x;
    const int w = t % WPR;
    const int rem = t / WPR;
    const int y = rem % IH;
    const int base = t - w;
    unsigned nbr = 0, e = 0;
#pragma unroll
    for (int dy = -1; dy <= 1; dy++) {
        const int yy = y + dy;
        if (yy < 0 || yy >= IH) continue;
        const int rb = base + dy * WPR;
        unsigned L = (w > 0)       ? g_pe0[rb + w - 1] : 0u;
        unsigned M =                 g_pe0[rb + w];
        unsigned R = (w < WPR - 1) ? g_pe0[rb + w + 1] : 0u;
        nbr |= hor3(L, M, R);
        if (dy == 0) e = M;
    }
    const unsigned l = g_pl0[t];
    const unsigned conn = nbr & l;
    g_pe1[t] = e | conn;
    g_pl1[t] = l & ~conn;
}

// ---------------------------------------------------------------------------
// Kernel 4: hysteresis iteration 2 + final edges*255 float store.
// ---------------------------------------------------------------------------
__global__ void k_hyst2(float* __restrict__ outE) {
    __shared__ float buf[256 * 33];
    const int t0 = blockIdx.x * 256;
    const int t = t0 + threadIdx.x;
    const int w = t % WPR;
    const int rem = t / WPR;
    const int y = rem % IH;
    const int base = t - w;
    unsigned nbr = 0, e = 0;
#pragma unroll
    for (int dy = -1; dy <= 1; dy++) {
        const int yy = y + dy;
        if (yy < 0 || yy >= IH) continue;
        const int rb = base + dy * WPR;
        unsigned L = (w > 0)       ? g_pe1[rb + w - 1] : 0u;
        unsigned M =                 g_pe1[rb + w];
        unsigned R = (w < WPR - 1) ? g_pe1[rb + w + 1] : 0u;
        nbr |= hor3(L, M, R);
        if (dy == 0) e = M;
    }
    const unsigned l = g_pl1[t];
    const unsigned enew = e | (nbr & l);
#pragma unroll
    for (int j = 0; j < 32; j++)
        buf[threadIdx.x * 33 + j] = ((enew >> j) & 1u) ? 255.0f : 0.0f;
    __syncthreads();
    const int gbase = t0 * 32;
#pragma unroll
    for (int i = 0; i < 32; i++) {
        const int k = i * 256 + threadIdx.x;
        outE[gbase + k] = buf[(k >> 5) * 33 + (k & 31)];
    }
}

extern "C" void kernel_launch(void* const* d_in, const int* in_sizes, int n_in,
                              void* d_out, int out_size) {
    const float* x = (const float*)d_in[0];
    float* out       = (float*)d_out;
    float* out_edges = out;
    float* out_mag   = out + NTOT;
    float* out_ang   = out + 2 * NTOT;

    dim3 blk(32, 8, 1);
    dim3 grd(IW / 32, IH / TH, IB);

    k_fused<<<grd, blk>>>(x, out_mag, out_ang);
    k_border<<<(IB * BORDER_WORDS_PER_IMG) / 8, blk>>>(out_mag);
    k_hyst1<<<NWORDS / 256, 256>>>();
    k_hyst2<<<NWORDS / 256, 256>>>(out_edges);
}

// round 10
// speedup vs baseline: 2.2322x; 1.1292x over previous
#include <cuda_runtime.h>

#define IW 1920
#define IH 1080
#define IB 8
#define NPIX (IW * IH)
#define NTOT (IB * NPIX)
#define WPR  (IW / 32)            // 60 packed words per row
#define NWORDS (NTOT / 32)        // 518400
#define BORDER_WORDS_PER_IMG (60 + 60 + 1078 * 2)   // 2276

#define TH 24                     // output tile height (1080/24 = 45)

// Scratch (no cudaMalloc allowed)
__device__ unsigned char g_dir[NTOT];
__device__ unsigned int  g_pe0[NWORDS], g_pl0[NWORDS];   // after NMS/threshold
__device__ unsigned int  g_pe1[NWORDS], g_pl1[NWORDS];   // after hysteresis iter 1

// Sobel with immediate weights (zero-weight terms skipped; original fmaf order).
__device__ __forceinline__ void sobel_win(float v00, float v01, float v02,
                                          float v10, float v12,
                                          float v20, float v21, float v22,
                                          float& gxv, float& gyv) {
    float gx = 0.f;
    gx = fmaf(-0.125f, v00, gx);
    gx = fmaf( 0.125f, v02, gx);
    gx = fmaf(-0.25f,  v10, gx);
    gx = fmaf( 0.25f,  v12, gx);
    gx = fmaf(-0.125f, v20, gx);
    gx = fmaf( 0.125f, v22, gx);
    float gy = 0.f;
    gy = fmaf(-0.125f, v00, gy);
    gy = fmaf(-0.25f,  v01, gy);
    gy = fmaf(-0.125f, v02, gy);
    gy = fmaf( 0.125f, v20, gy);
    gy = fmaf( 0.25f,  v21, gy);
    gy = fmaf( 0.125f, v22, gy);
    gxv = gx; gyv = gy;
}

// Window top-left = (r, c): reads gsm[r..r+2][c..c+2].
__device__ __forceinline__ void sobel_px(const float (*gsm)[40], int r, int c,
                                         float& gxv, float& gyv) {
    sobel_win(gsm[r+0][c+0], gsm[r+0][c+1], gsm[r+0][c+2],
              gsm[r+1][c+0],                gsm[r+1][c+2],
              gsm[r+2][c+0], gsm[r+2][c+1], gsm[r+2][c+2], gxv, gyv);
}

// ang/deg/cls chain — bit-identical to previous rounds.
__device__ __forceinline__ void ang_chain(float gx_, float gy_, float& am, int& cls) {
    float ang = atan2f(gy_, gx_);
    float t = ang + 3.14159274101257324f;            // float32(pi)
    if (t >= 6.28318548202514648f) t -= 6.28318548202514648f;   // == fmodf(t, 2pi)
    float deg = t * 57.2957801818847656f;            // float32(180/pi)
    am = deg;
    if (am >= 180.0f) am -= 180.0f;                  // == fmodf(deg, 180)
    if (am >= 180.0f) am -= 180.0f;
    int q = (int)rintf(deg / 45.0f);                 // round-half-even == jnp.round
    cls = q & 3;
}

// ---------------------------------------------------------------------------
// Kernel 1: fused gaussian(5x5) + sobel + mag*255 + ang + NMS + threshold.
// Interior-block fast path; 4-col-blocked sobel stage with wide STG.128
// stores of mag/ang; slim NMS stage.
// Border words (jnp.roll wrap) recomputed by k_border afterwards.
// ---------------------------------------------------------------------------
__global__ void k_fused(const float* __restrict__ x,
                        float* __restrict__ magOut, float* __restrict__ angOut) {
    // gaussian = [[2,4,5,4,2],[4,9,12,9,4],[5,12,15,12,5],[4,9,12,9,4],[2,4,5,4,2]]/159
    constexpr float GW[25] = {
        2.0f/159.0f, 4.0f/159.0f,  5.0f/159.0f, 4.0f/159.0f, 2.0f/159.0f,
        4.0f/159.0f, 9.0f/159.0f, 12.0f/159.0f, 9.0f/159.0f, 4.0f/159.0f,
        5.0f/159.0f,12.0f/159.0f, 15.0f/159.0f,12.0f/159.0f, 5.0f/159.0f,
        4.0f/159.0f, 9.0f/159.0f, 12.0f/159.0f, 9.0f/159.0f, 4.0f/159.0f,
        2.0f/159.0f, 4.0f/159.0f,  5.0f/159.0f, 4.0f/159.0f, 2.0f/159.0f };
    __shared__ float sin_[32][40];     // raw input, rows by-4..by+27, cols bx-4..bx+35
    __shared__ float gsm[28][40];      // smoothed/255, row r <-> Y=by+r-2, col c <-> X=bx+c-2 (36 used)
    __shared__ float magS[26][40];     // mag*255, row r <-> Y=by+r-1, col c <-> X=bx+c-4 (c 3..36 used)
    __shared__ unsigned int dirS[24][8]; // packed cls, 4 px per word
    const int b  = blockIdx.z;
    const int bx = blockIdx.x * 32, by = blockIdx.y * TH;
    const int tx = threadIdx.x, ty = threadIdx.y;
    const int tid = ty * 32 + tx;
    const float* img = x + b * NPIX;
    const bool interior = (blockIdx.x > 0) & (blockIdx.x < 59) &
                          (blockIdx.y > 0) & (blockIdx.y < 44);
    // ---- stage 0: raw input tile ----
    if (interior) {
#pragma unroll
        for (int k = 0; k < 4; k++) {
            const int r = ty + 8 * k;
            const int yy = by + r - 4;
            sin_[r][tx] = img[yy * IW + (bx + tx - 4)];
            if (tx < 8) sin_[r][tx + 32] = img[yy * IW + (bx + tx + 28)];
        }
    } else {
#pragma unroll
        for (int k = 0; k < 4; k++) {
            const int r = ty + 8 * k;
            const int yy = by + r - 4;
            {
                const int xx = bx + tx - 4;
                float v = 0.f;
                if (yy >= 0 && yy < IH && xx >= 0 && xx < IW) v = img[yy * IW + xx];
                sin_[r][tx] = v;
            }
            if (tx < 8) {
                const int xx = bx + tx + 28;
                float v = 0.f;
                if (yy >= 0 && yy < IH && xx >= 0 && xx < IW) v = img[yy * IW + xx];
                sin_[r][tx + 32] = v;
            }
        }
    }
    __syncthreads();
    // ---- stage 1: gaussian, 4 outputs per thread (28 rows x 9 groups = 252) ----
    if (tid < 252) {
        const int r = tid / 9;
        const int c0 = (tid - r * 9) * 4;
        float W[5][8];
#pragma unroll
        for (int di = 0; di < 5; di++) {
            const float4 lo = *(const float4*)&sin_[r + di][c0];
            const float4 hi = *(const float4*)&sin_[r + di][c0 + 4];
            W[di][0] = lo.x; W[di][1] = lo.y; W[di][2] = lo.z; W[di][3] = lo.w;
            W[di][4] = hi.x; W[di][5] = hi.y; W[di][6] = hi.z; W[di][7] = hi.w;
        }
        float s0 = 0.f, s1 = 0.f, s2 = 0.f, s3 = 0.f;
#pragma unroll
        for (int di = 0; di < 5; di++)
#pragma unroll
            for (int dj = 0; dj < 5; dj++) {
                const float wgt = GW[di * 5 + dj];
                s0 = fmaf(wgt, W[di][dj + 0], s0);
                s1 = fmaf(wgt, W[di][dj + 1], s1);
                s2 = fmaf(wgt, W[di][dj + 2], s2);
                s3 = fmaf(wgt, W[di][dj + 3], s3);
            }
        float4 o;
        if (interior) {
            o.x = s0 * (1.0f / 255.0f);
            o.y = s1 * (1.0f / 255.0f);
            o.z = s2 * (1.0f / 255.0f);
            o.w = s3 * (1.0f / 255.0f);
        } else {
            const int yy = by + r - 2;
            const bool rowOk = (yy >= 0 && yy < IH);
            const int xx0 = bx + c0 - 2;
            o.x = (rowOk && xx0 + 0 >= 0 && xx0 + 0 < IW) ? s0 * (1.0f / 255.0f) : 0.f;
            o.y = (rowOk && xx0 + 1 >= 0 && xx0 + 1 < IW) ? s1 * (1.0f / 255.0f) : 0.f;
            o.z = (rowOk && xx0 + 2 >= 0 && xx0 + 2 < IW) ? s2 * (1.0f / 255.0f) : 0.f;
            o.w = (rowOk && xx0 + 3 >= 0 && xx0 + 3 < IW) ? s3 * (1.0f / 255.0f) : 0.f;
        }
        *(float4*)&gsm[r][c0] = o;
    }
    __syncthreads();
    // ---- stage 2a: interior 4-col groups (24 rows x 8 groups = 192 threads) ----
    // magS row r <-> image Y = by + r - 1; window top-left gsm row must be r
    // (gsm row of Y-1 is (Y-1)-by+2 = r). Window rows = r, r+1, r+2.
    const bool colBorder = (blockIdx.x == 0) | (blockIdx.x == WPR - 1);
    if (tid < 192) {
        const int r = (tid >> 3) + 1;          // 1..24
        const int k = tid & 7;                 // 0..7
        float w0[8], w1[8], w2[8];
        {
            const float4 a0 = *(const float4*)&gsm[r][4 * k];
            const float4 a1 = *(const float4*)&gsm[r][4 * k + 4];
            w0[0]=a0.x; w0[1]=a0.y; w0[2]=a0.z; w0[3]=a0.w;
            w0[4]=a1.x; w0[5]=a1.y; w0[6]=a1.z; w0[7]=a1.w;
            const float4 b0 = *(const float4*)&gsm[r + 1][4 * k];
            const float4 b1 = *(const float4*)&gsm[r + 1][4 * k + 4];
            w1[0]=b0.x; w1[1]=b0.y; w1[2]=b0.z; w1[3]=b0.w;
            w1[4]=b1.x; w1[5]=b1.y; w1[6]=b1.z; w1[7]=b1.w;
            const float4 c0_ = *(const float4*)&gsm[r + 2][4 * k];
            const float4 c1_ = *(const float4*)&gsm[r + 2][4 * k + 4];
            w2[0]=c0_.x; w2[1]=c0_.y; w2[2]=c0_.z; w2[3]=c0_.w;
            w2[4]=c1_.x; w2[5]=c1_.y; w2[6]=c1_.z; w2[7]=c1_.w;
        }
        float mg[4], an[4];
        unsigned int clsPack = 0;
#pragma unroll
        for (int j = 0; j < 4; j++) {
            float gx_, gy_;
            sobel_win(w0[j+1], w0[j+2], w0[j+3],
                      w1[j+1],          w1[j+3],
                      w2[j+1], w2[j+2], w2[j+3], gx_, gy_);
            mg[j] = sqrtf(gx_ * gx_ + gy_ * gy_ + 1e-6f) * 255.0f;
            float am; int cls;
            ang_chain(gx_, gy_, am, cls);
            an[j] = am;
            clsPack |= (unsigned)cls << (8 * j);
        }
        // stage mag into smem for NMS
        *(float4*)&magS[r][4 * k + 4] = make_float4(mg[0], mg[1], mg[2], mg[3]);
        dirS[r - 1][k] = clsPack;
        // wide global stores
        const int Y = by + r - 1;
        const int idx = b * NPIX + Y * IW + bx + 4 * k;
        *(float4*)&magOut[idx] = make_float4(mg[0], mg[1], mg[2], mg[3]);
        *(float4*)&angOut[idx] = make_float4(an[0], an[1], an[2], an[3]);
        if (Y == 0 || Y == IH - 1 || colBorder) {
            uchar4 d4;
            d4.x = (unsigned char)(clsPack & 3);
            d4.y = (unsigned char)((clsPack >> 8) & 3);
            d4.z = (unsigned char)((clsPack >> 16) & 3);
            d4.w = (unsigned char)((clsPack >> 24) & 3);
            *(uchar4*)&g_dir[idx] = d4;
        }
    }
    // ---- stage 2b: magS halo ring (rows 0 & 25 cols 3..36; cols 3 & 36 rows 1..24) ----
    if (tid < 116) {
        int r, c;
        if (tid < 34)      { r = 0;         c = 3 + tid; }
        else if (tid < 68) { r = 25;        c = 3 + (tid - 34); }
        else if (tid < 92) { r = tid - 67;  c = 3; }          // rows 1..24
        else               { r = tid - 91;  c = 36; }         // rows 1..24
        float gxv, gyv;
        sobel_px(gsm, r, c - 3, gxv, gyv);     // window rows r..r+2, cols c-3..c-1
        magS[r][c] = sqrtf(gxv * gxv + gyv * gyv + 1e-6f) * 255.0f;
    }
    __syncthreads();
    // ---- stage 3: NMS only (3 rows per thread) ----
#pragma unroll
    for (int s = 0; s < 3; s++) {
        const int o = ty + 8 * s;            // output row within tile (warp-uniform)
        const int Y = by + o;
        const int r0 = o + 1, c0 = tx + 4;   // magS coords of own pixel
        const float m255 = magS[r0][c0];
        const int cls = (int)((dirS[o][tx >> 2] >> (8 * (tx & 3))) & 3u);
        // cls0: (y,xr)/(y,xl)  cls1: (yd,xr)/(yu,x) [ref bug kept]
        // cls2: (yd,x)/(yu,x)  cls3: (yd,xl)/(yu,xr)
        int ar = (cls == 0) ? r0 : r0 + 1;
        int ac = (cls == 2) ? c0 : ((cls == 3) ? c0 - 1 : c0 + 1);
        int cr = (cls == 0) ? r0 : r0 - 1;
        int cc = (cls == 0) ? c0 - 1 : ((cls == 3) ? c0 + 1 : c0);
        float a = magS[ar][ac];
        float c = magS[cr][cc];
        float sup = (m255 > a && m255 > c) ? m255 : 0.f;
        unsigned we = __ballot_sync(0xffffffffu, sup > 150.0f);
        unsigned wl = __ballot_sync(0xffffffffu, sup >= 50.0f && sup < 150.0f);
        if (tx == 0) {
            const int widx = (b * IH + Y) * WPR + blockIdx.x;
            g_pe0[widx] = we;
            g_pl0[widx] = wl;
        }
    }
}

// ---------------------------------------------------------------------------
// Kernel 2: recompute NMS/threshold for border words (rows 0 & 1079, word
// cols 0 & 59) with jnp.roll wrap-around. One warp per word.
// ---------------------------------------------------------------------------
__global__ void k_border(const float* __restrict__ mag) {
    const int W = blockIdx.x * 8 + threadIdx.y;          // warp id
    const int lane = threadIdx.x;
    const int b = W / BORDER_WORDS_PER_IMG;
    const int u = W % BORDER_WORDS_PER_IMG;
    int y, w;
    if (u < 60)       { y = 0;        w = u; }
    else if (u < 120) { y = IH - 1;   w = u - 60; }
    else { int v = u - 120; y = 1 + (v >> 1); w = (v & 1) ? (WPR - 1) : 0; }
    const int x = w * 32 + lane;
    const float* p = mag + b * NPIX;
    const int idx = b * NPIX + y * IW + x;
    const float m0 = p[y * IW + x];
    const int xl = (x == 0) ? (IW - 1) : (x - 1);
    const int xr = (x == IW - 1) ? 0 : (x + 1);
    const int yu = (y == 0) ? (IH - 1) : (y - 1);
    const int yd = (y == IH - 1) ? 0 : (y + 1);
    const int cls = g_dir[idx];
    int ay = (cls == 0) ? y : yd;
    int ax = (cls == 2) ? x : ((cls == 3) ? xl : xr);
    int cy = (cls == 0) ? y : yu;
    int cx = (cls == 0) ? xl : ((cls == 3) ? xr : x);
    float a = p[ay * IW + ax];
    float c = p[cy * IW + cx];
    float sup = (m0 > a && m0 > c) ? m0 : 0.f;
    unsigned we = __ballot_sync(0xffffffffu, sup > 150.0f);
    unsigned wl = __ballot_sync(0xffffffffu, sup >= 50.0f && sup < 150.0f);
    if (lane == 0) {
        const int widx = (b * IH + y) * WPR + w;
        g_pe0[widx] = we;
        g_pl0[widx] = wl;
    }
}

// ---------------------------------------------------------------------------
// Bit helper: OR of {left,center,right} horizontal neighbors of a word row.
// ---------------------------------------------------------------------------
__device__ __forceinline__ unsigned hor3(unsigned L, unsigned M, unsigned R) {
    return M | (M << 1) | (M >> 1) | (L >> 31) | (R << 31);
}

// ---------------------------------------------------------------------------
// Kernel 3: hysteresis iteration 1, fully bit-packed, word per thread.
// ---------------------------------------------------------------------------
__global__ void k_hyst1() {
    const int t = blockIdx.x * 256 + threadIdx.x;
    const int w = t % WPR;
    const int rem = t / WPR;
    const int y = rem % IH;
    const int base = t - w;
    unsigned nbr = 0, e = 0;
#pragma unroll
    for (int dy = -1; dy <= 1; dy++) {
        const int yy = y + dy;
        if (yy < 0 || yy >= IH) continue;
        const int rb = base + dy * WPR;
        unsigned L = (w > 0)       ? g_pe0[rb + w - 1] : 0u;
        unsigned M =                 g_pe0[rb + w];
        unsigned R = (w < WPR - 1) ? g_pe0[rb + w + 1] : 0u;
        nbr |= hor3(L, M, R);
        if (dy == 0) e = M;
    }
    const unsigned l = g_pl0[t];
    const unsigned conn = nbr & l;
    g_pe1[t] = e | conn;
    g_pl1[t] = l & ~conn;
}

// ---------------------------------------------------------------------------
// Kernel 4: hysteresis iteration 2 + final edges*255 float store.
// ---------------------------------------------------------------------------
__global__ void k_hyst2(float* __restrict__ outE) {
    __shared__ float buf[256 * 33];
    const int t0 = blockIdx.x * 256;
    const int t = t0 + threadIdx.x;
    const int w = t % WPR;
    const int rem = t / WPR;
    const int y = rem % IH;
    const int base = t - w;
    unsigned nbr = 0, e = 0;
#pragma unroll
    for (int dy = -1; dy <= 1; dy++) {
        const int yy = y + dy;
        if (yy < 0 || yy >= IH) continue;
        const int rb = base + dy * WPR;
        unsigned L = (w > 0)       ? g_pe1[rb + w - 1] : 0u;
        unsigned M =                 g_pe1[rb + w];
        unsigned R = (w < WPR - 1) ? g_pe1[rb + w + 1] : 0u;
        nbr |= hor3(L, M, R);
        if (dy == 0) e = M;
    }
    const unsigned l = g_pl1[t];
    const unsigned enew = e | (nbr & l);
#pragma unroll
    for (int j = 0; j < 32; j++)
        buf[threadIdx.x * 33 + j] = ((enew >> j) & 1u) ? 255.0f : 0.0f;
    __syncthreads();
    const int gbase = t0 * 32;
#pragma unroll
    for (int i = 0; i < 32; i++) {
        const int k = i * 256 + threadIdx.x;
        outE[gbase + k] = buf[(k >> 5) * 33 + (k & 31)];
    }
}

extern "C" void kernel_launch(void* const* d_in, const int* in_sizes, int n_in,
                              void* d_out, int out_size) {
    const float* x = (const float*)d_in[0];
    float* out       = (float*)d_out;
    float* out_edges = out;
    float* out_mag   = out + NTOT;
    float* out_ang   = out + 2 * NTOT;

    dim3 blk(32, 8, 1);
    dim3 grd(IW / 32, IH / TH, IB);

    k_fused<<<grd, blk>>>(x, out_mag, out_ang);
    k_border<<<(IB * BORDER_WORDS_PER_IMG) / 8, blk>>>(out_mag);
    k_hyst1<<<NWORDS / 256, 256>>>();
    k_hyst2<<<NWORDS / 256, 256>>>(out_edges);
}